// round 2
// baseline (speedup 1.0000x reference)
#include <cuda_runtime.h>
#include <cuda_bf16.h>
#include <cstdint>

// ---------------------------------------------------------------------------
// contrastive_mse_cosinedistance: fused cosine-Gram + softmax-KL
//   a_ij = -<xcd_i, xcd_j>/(|..||..|),  b_ij = -<xed_i, xed_j>/(..)
//   kl_i = W_i/SA_i - ln SA_i + ln SB_i,
//     SA = sum_j e^{a_ij}, SB = sum_j e^{b_ij}, W = sum_j e^{a_ij}(a_ij-b_ij)
//   out  = mean_i kl_i
// (softmax shift-invariance removes the "1 - sim"; bounded logits remove the
//  running-max bookkeeping entirely)
// ---------------------------------------------------------------------------

namespace {
constexpr int N  = 4096;
constexpr int D  = 512;
constexpr int BM = 128;          // CTA i-tile
constexpr int BN = 64;           // CTA j-tile
constexpr int BK = 16;           // k-step (one mma K)
constexpr int NJ = 16;           // j-splits (grid.y)
constexpr int JT = (N / NJ) / BN;  // 4 j-tiles per CTA
constexpr int KS = D / BK;       // 32 k-steps
constexpr int PAD = 24;          // halves per smem row (48B: conflict-free ldmatrix)
}

// static scratch (no allocations allowed in kernel_launch)
__device__ __nv_bfloat16 g_bf[2][N * D];     // normalized bf16 copies (8 MB, L2-resident)
__device__ float g_part[3][NJ][N];           // per (stat, j-split, row) partials

// exp(x) for |x| <= ~1.3 : degree-9 Taylor, FMA-pipe only, rel err < 4e-6
__device__ __forceinline__ float fast_exp(float x) {
    float p = fmaf(2.7557319e-6f, x, 2.4801587e-5f);
    p = fmaf(p, x, 1.9841270e-4f);
    p = fmaf(p, x, 1.3888889e-3f);
    p = fmaf(p, x, 8.3333333e-3f);
    p = fmaf(p, x, 4.1666667e-2f);
    p = fmaf(p, x, 1.6666667e-1f);
    p = fmaf(p, x, 0.5f);
    p = fmaf(p, x, 1.0f);
    p = fmaf(p, x, 1.0f);
    return p;
}

__device__ __forceinline__ void ldsm_x4(uint32_t (&r)[4], const void* ptr) {
    uint32_t addr = (uint32_t)__cvta_generic_to_shared(ptr);
    asm volatile("ldmatrix.sync.aligned.m8n8.x4.shared.b16 {%0,%1,%2,%3}, [%4];\n"
                 : "=r"(r[0]), "=r"(r[1]), "=r"(r[2]), "=r"(r[3])
                 : "r"(addr));
}

__device__ __forceinline__ void mma_bf16(float (&c)[4], const uint32_t (&a)[4],
                                         uint32_t b0, uint32_t b1) {
    asm volatile(
        "mma.sync.aligned.m16n8k16.row.col.f32.bf16.bf16.f32 "
        "{%0,%1,%2,%3}, {%4,%5,%6,%7}, {%8,%9}, {%0,%1,%2,%3};\n"
        : "+f"(c[0]), "+f"(c[1]), "+f"(c[2]), "+f"(c[3])
        : "r"(a[0]), "r"(a[1]), "r"(a[2]), "r"(a[3]), "r"(b0), "r"(b1));
}

// ---------------------------------------------------------------------------
// Kernel 1: row-normalize (eps clamp) both matrices, emit bf16
// grid (4096, 2), block 128
// ---------------------------------------------------------------------------
__global__ void normalize_kernel(const float* __restrict__ in0,
                                 const float* __restrict__ in1) {
    const int row = blockIdx.x;
    const int mat = blockIdx.y;
    const float* src = (mat == 0) ? in0 : in1;
    const float4 x =
        reinterpret_cast<const float4*>(src + (size_t)row * D)[threadIdx.x];
    float ss = x.x * x.x + x.y * x.y + x.z * x.z + x.w * x.w;
#pragma unroll
    for (int o = 16; o > 0; o >>= 1) ss += __shfl_xor_sync(0xffffffffu, ss, o);
    __shared__ float ws[4];
    if ((threadIdx.x & 31) == 0) ws[threadIdx.x >> 5] = ss;
    __syncthreads();
    ss = ws[0] + ws[1] + ws[2] + ws[3];
    const float inv = 1.0f / fmaxf(sqrtf(ss), 1e-8f);
    __nv_bfloat162* dst =
        reinterpret_cast<__nv_bfloat162*>(&g_bf[mat][(size_t)row * D]);
    dst[threadIdx.x * 2 + 0] = __floats2bfloat162_rn(x.x * inv, x.y * inv);
    dst[threadIdx.x * 2 + 1] = __floats2bfloat162_rn(x.z * inv, x.w * inv);
}

// ---------------------------------------------------------------------------
// Kernel 2: fused dual-Gram GEMM + KL partial sums
// grid (N/BM=32, NJ=16), block 256 (8 warps: 4 m-strips x 2 n-strips)
// warp tile 32x32 per Gram; mma m16n8k16 bf16->f32
// ---------------------------------------------------------------------------
__global__ void __launch_bounds__(256) gram_kl_kernel() {
    __shared__ __align__(16) __nv_bfloat16 sA[2][2][BM][PAD];  // [buf][mat][m][k]
    __shared__ __align__(16) __nv_bfloat16 sB[2][2][BN][PAD];  // [buf][mat][n][k]
    __shared__ float sred[3][BM];

    const int t = threadIdx.x;
    const int lane = t & 31;
    const int warp = t >> 5;
    const int wm = warp >> 1;          // 0..3
    const int wn = warp & 1;           // 0..1
    const int g = lane >> 2;           // 0..7
    const int tg = lane & 3;           // 0..3
    const int i0 = blockIdx.x * BM;
    const int js = blockIdx.y;
    const int j0base = js * (N / NJ);

    // global->smem copy assignments (16B vectors of 8 halves)
    const int arow = t >> 1, akv = t & 1;                    // A: both mats
    const int bmat = t >> 7, brow = (t & 127) >> 1, bkv = t & 1;  // B: split mats

    const int lrow = lane & 15;        // ldmatrix row within a 16-row tile
    const int lcol = (lane >> 4) * 8;  // 0 or 8 (k-halves)

    float SAr[4] = {0.f, 0.f, 0.f, 0.f};
    float Wr[4]  = {0.f, 0.f, 0.f, 0.f};
    float SBr[4] = {0.f, 0.f, 0.f, 0.f};

    for (int jt = 0; jt < JT; ++jt) {
        const int j0 = j0base + jt * BN;

        float acc[2][2][4][4];  // [mat][tm][tn][c]
#pragma unroll
        for (int m2 = 0; m2 < 2; ++m2)
#pragma unroll
            for (int tm = 0; tm < 2; ++tm)
#pragma unroll
                for (int tn = 0; tn < 4; ++tn)
#pragma unroll
                    for (int c = 0; c < 4; ++c) acc[m2][tm][tn][c] = 0.f;

        uint4 ra0, ra1, rb;
        // preload k-step 0 into buffer 0
        ra0 = *reinterpret_cast<const uint4*>(
            &g_bf[0][(size_t)(i0 + arow) * D + akv * 8]);
        ra1 = *reinterpret_cast<const uint4*>(
            &g_bf[1][(size_t)(i0 + arow) * D + akv * 8]);
        rb = *reinterpret_cast<const uint4*>(
            &g_bf[bmat][(size_t)(j0 + brow) * D + bkv * 8]);
        *reinterpret_cast<uint4*>(&sA[0][0][arow][akv * 8]) = ra0;
        *reinterpret_cast<uint4*>(&sA[0][1][arow][akv * 8]) = ra1;
        *reinterpret_cast<uint4*>(&sB[0][bmat][brow][bkv * 8]) = rb;
        __syncthreads();

        for (int ks = 0; ks < KS; ++ks) {
            const int cur = ks & 1;
            const int nxt = cur ^ 1;
            if (ks + 1 < KS) {
                const int kk = (ks + 1) * BK;
                ra0 = *reinterpret_cast<const uint4*>(
                    &g_bf[0][(size_t)(i0 + arow) * D + kk + akv * 8]);
                ra1 = *reinterpret_cast<const uint4*>(
                    &g_bf[1][(size_t)(i0 + arow) * D + kk + akv * 8]);
                rb = *reinterpret_cast<const uint4*>(
                    &g_bf[bmat][(size_t)(j0 + brow) * D + kk + bkv * 8]);
            }

            uint32_t af[2][2][4];   // [mat][tm][reg]
            uint32_t bfr[2][4][2];  // [mat][tn][reg]
#pragma unroll
            for (int m2 = 0; m2 < 2; ++m2) {
#pragma unroll
                for (int tm = 0; tm < 2; ++tm)
                    ldsm_x4(af[m2][tm], &sA[cur][m2][wm * 32 + tm * 16 + lrow][lcol]);
#pragma unroll
                for (int tp = 0; tp < 2; ++tp) {
                    uint32_t r[4];
                    ldsm_x4(r, &sB[cur][m2][wn * 32 + tp * 16 + lrow][lcol]);
                    bfr[m2][tp * 2 + 0][0] = r[0];
                    bfr[m2][tp * 2 + 0][1] = r[2];
                    bfr[m2][tp * 2 + 1][0] = r[1];
                    bfr[m2][tp * 2 + 1][1] = r[3];
                }
            }
#pragma unroll
            for (int m2 = 0; m2 < 2; ++m2)
#pragma unroll
                for (int tm = 0; tm < 2; ++tm)
#pragma unroll
                    for (int tn = 0; tn < 4; ++tn)
                        mma_bf16(acc[m2][tm][tn], af[m2][tm],
                                 bfr[m2][tn][0], bfr[m2][tn][1]);

            if (ks + 1 < KS) {
                *reinterpret_cast<uint4*>(&sA[nxt][0][arow][akv * 8]) = ra0;
                *reinterpret_cast<uint4*>(&sA[nxt][1][arow][akv * 8]) = ra1;
                *reinterpret_cast<uint4*>(&sB[nxt][bmat][brow][bkv * 8]) = rb;
            }
            __syncthreads();
        }

        // fused epilogue: polynomial exp + per-row partial sums (registers only)
#pragma unroll
        for (int tm = 0; tm < 2; ++tm)
#pragma unroll
            for (int tn = 0; tn < 4; ++tn)
#pragma unroll
                for (int c = 0; c < 4; ++c) {
                    const int li = tm * 2 + (c >> 1);
                    const float a = -acc[0][tm][tn][c];
                    const float b = -acc[1][tm][tn][c];
                    const float ea = fast_exp(a);
                    const float eb = fast_exp(b);
                    SAr[li] += ea;
                    SBr[li] += eb;
                    Wr[li] = fmaf(ea, a - b, Wr[li]);
                }
    }

    // reduce across the 4 tg-lanes sharing each row (butterfly)
#pragma unroll
    for (int li = 0; li < 4; ++li) {
#pragma unroll
        for (int off = 1; off < 4; off <<= 1) {
            SAr[li] += __shfl_xor_sync(0xffffffffu, SAr[li], off);
            Wr[li]  += __shfl_xor_sync(0xffffffffu, Wr[li], off);
            SBr[li] += __shfl_xor_sync(0xffffffffu, SBr[li], off);
        }
    }
    __syncthreads();
    // combine the two n-strip warps in fixed order (deterministic)
    if (wn == 0 && tg == 0) {
#pragma unroll
        for (int li = 0; li < 4; ++li) {
            const int r = wm * 32 + (li >> 1) * 16 + (li & 1) * 8 + g;
            sred[0][r] = SAr[li];
            sred[1][r] = Wr[li];
            sred[2][r] = SBr[li];
        }
    }
    __syncthreads();
    if (wn == 1 && tg == 0) {
#pragma unroll
        for (int li = 0; li < 4; ++li) {
            const int r = wm * 32 + (li >> 1) * 16 + (li & 1) * 8 + g;
            sred[0][r] += SAr[li];
            sred[1][r] += Wr[li];
            sred[2][r] += SBr[li];
        }
    }
    __syncthreads();
    if (t < BM) {
        const int row = i0 + t;
        g_part[0][js][row] = sred[0][t];
        g_part[1][js][row] = sred[1][t];
        g_part[2][js][row] = sred[2][t];
    }
}

// ---------------------------------------------------------------------------
// Kernel 3: merge j-split partials, per-row KL, deterministic mean
// ---------------------------------------------------------------------------
__global__ void finalize_kernel(float* __restrict__ out) {
    __shared__ float red[256];
    const int t = threadIdx.x;
    float sum = 0.f;
    for (int r = t; r < N; r += 256) {
        float SA = 0.f, W = 0.f, SB = 0.f;
#pragma unroll
        for (int j = 0; j < NJ; ++j) {
            SA += g_part[0][j][r];
            W  += g_part[1][j][r];
            SB += g_part[2][j][r];
        }
        sum += W / SA - logf(SA) + logf(SB);
    }
    red[t] = sum;
    __syncthreads();
    for (int s = 128; s > 0; s >>= 1) {
        if (t < s) red[t] += red[t + s];
        __syncthreads();
    }
    if (t == 0) out[0] = red[0] * (1.0f / (float)N);
}

// ---------------------------------------------------------------------------
extern "C" void kernel_launch(void* const* d_in, const int* in_sizes, int n_in,
                              void* d_out, int out_size) {
    (void)in_sizes; (void)n_in; (void)out_size;
    const float* cd = (const float*)d_in[0];   // cosine_distance_latent (target)
    const float* ed = (const float*)d_in[1];   // mse_latent (predicted)
    normalize_kernel<<<dim3(N, 2), 128>>>(cd, ed);
    gram_kl_kernel<<<dim3(N / BM, NJ), 256>>>();
    finalize_kernel<<<1, 256>>>((float*)d_out);
}

// round 4
// speedup vs baseline: 1.1403x; 1.1403x over previous
#include <cuda_runtime.h>
#include <cuda_bf16.h>
#include <cstdint>

// ---------------------------------------------------------------------------
// contrastive_mse_cosinedistance — pipelined mma.sync edition (compute_100 base;
// tcgen05 unavailable in this toolchain: ptxas target rejects sm_100a ISA).
//   logits a = -<xn_i,xn_j>, b likewise; per row SA=Σe^a, SB=Σe^b,
//   W=Σe^a(a-b); kl = W/SA - ln SA + ln SB; out = mean_i kl.
// Gram kernel: CTA 128x64, 4 j-tiles, BK=16, 3-stage cp.async pipeline,
// conflict-free [mat][kvhalf][row][16B] smem layout, dual-gram mma m16n8k16.
// ---------------------------------------------------------------------------

namespace {
constexpr int N  = 4096;
constexpr int D  = 512;
constexpr int BM = 128;
constexpr int BN = 64;
constexpr int NJ = 16;             // j-splits (grid.y)
constexpr int JT = (N / NJ) / BN;  // 4 j-tiles per CTA
constexpr int KS = D / 16;         // 32 k-steps of BK=16
constexpr int ST = 3;              // pipeline stages
constexpr int A_STAGE = 2 * 2 * BM * 16;  // bytes: mats x kvhalf x rows x 16B = 8192
constexpr int B_STAGE = 2 * 2 * BN * 16;  // 4096
}

__device__ __nv_bfloat16 g_bf[2][N * D];  // normalized bf16 (8 MB, L2-resident)
__device__ float g_part[3][NJ][N];        // (stat, j-split, row) partials

// exp(x) for |x| <= ~1.3 : degree-9 Taylor, FMA-pipe only, rel err < 4e-6
__device__ __forceinline__ float fast_exp(float x) {
    float p = fmaf(2.7557319e-6f, x, 2.4801587e-5f);
    p = fmaf(p, x, 1.9841270e-4f);
    p = fmaf(p, x, 1.3888889e-3f);
    p = fmaf(p, x, 8.3333333e-3f);
    p = fmaf(p, x, 4.1666667e-2f);
    p = fmaf(p, x, 1.6666667e-1f);
    p = fmaf(p, x, 0.5f);
    p = fmaf(p, x, 1.0f);
    p = fmaf(p, x, 1.0f);
    return p;
}

__device__ __forceinline__ void ldsm_x4(uint32_t (&r)[4], uint32_t addr) {
    asm volatile("ldmatrix.sync.aligned.m8n8.x4.shared.b16 {%0,%1,%2,%3}, [%4];\n"
                 : "=r"(r[0]), "=r"(r[1]), "=r"(r[2]), "=r"(r[3])
                 : "r"(addr));
}

__device__ __forceinline__ void mma_bf16(float (&c)[4], const uint32_t (&a)[4],
                                         uint32_t b0, uint32_t b1) {
    asm volatile(
        "mma.sync.aligned.m16n8k16.row.col.f32.bf16.bf16.f32 "
        "{%0,%1,%2,%3}, {%4,%5,%6,%7}, {%8,%9}, {%0,%1,%2,%3};\n"
        : "+f"(c[0]), "+f"(c[1]), "+f"(c[2]), "+f"(c[3])
        : "r"(a[0]), "r"(a[1]), "r"(a[2]), "r"(a[3]), "r"(b0), "r"(b1));
}

__device__ __forceinline__ void cp16(uint32_t dst, const void* src) {
    asm volatile("cp.async.cg.shared.global [%0], [%1], 16;\n"
                 :: "r"(dst), "l"(src) : "memory");
}

// ---------------------------------------------------------------------------
// Kernel 1: row-normalize (eps clamp) both matrices, emit bf16
// ---------------------------------------------------------------------------
__global__ void normalize_kernel(const float* __restrict__ in0,
                                 const float* __restrict__ in1) {
    const int row = blockIdx.x;
    const int mat = blockIdx.y;
    const float* src = (mat == 0) ? in0 : in1;
    const float4 x =
        reinterpret_cast<const float4*>(src + (size_t)row * D)[threadIdx.x];
    float ss = x.x * x.x + x.y * x.y + x.z * x.z + x.w * x.w;
#pragma unroll
    for (int o = 16; o > 0; o >>= 1) ss += __shfl_xor_sync(0xffffffffu, ss, o);
    __shared__ float ws[4];
    if ((threadIdx.x & 31) == 0) ws[threadIdx.x >> 5] = ss;
    __syncthreads();
    ss = ws[0] + ws[1] + ws[2] + ws[3];
    const float inv = 1.0f / fmaxf(sqrtf(ss), 1e-8f);
    __nv_bfloat162* dst =
        reinterpret_cast<__nv_bfloat162*>(&g_bf[mat][(size_t)row * D]);
    dst[threadIdx.x * 2 + 0] = __floats2bfloat162_rn(x.x * inv, x.y * inv);
    dst[threadIdx.x * 2 + 1] = __floats2bfloat162_rn(x.z * inv, x.w * inv);
}

// ---------------------------------------------------------------------------
// Kernel 2: pipelined dual-Gram GEMM + fused KL partials
// grid (N/BM=32, NJ=16), block 256 (8 warps: 4 m-strips x 2 n-strips)
// ---------------------------------------------------------------------------
__global__ void __launch_bounds__(256, 1) gram_kl_kernel() {
    // stage layout: [stage][mat][kvhalf][row][16B] — all 32 banks hit once for
    // both cp.async stores and ldmatrix reads (no padding, no conflicts)
    __shared__ __align__(16) char sA[ST * A_STAGE];
    __shared__ __align__(16) char sB[ST * B_STAGE];
    __shared__ float sred[3][BM];

    const int t = threadIdx.x;
    const int lane = t & 31;
    const int warp = t >> 5;
    const int wm = warp >> 1;  // 0..3
    const int wn = warp & 1;   // 0..1
    const int g = lane >> 2;
    const int tg = lane & 3;
    const int i0 = blockIdx.x * BM;
    const int js = blockIdx.y;
    const int j0base = js * (N / NJ);

    const uint32_t aBase = (uint32_t)__cvta_generic_to_shared(sA);
    const uint32_t bBase = (uint32_t)__cvta_generic_to_shared(sB);

    // producer mapping (16B vectors)
    const int r2 = t >> 1, kvb = t & 1;                          // A rows
    const int bmat = t >> 7, brow = (t & 127) >> 1, bkv = t & 1; // B rows

    // consumer (ldmatrix) mapping
    const int lrow = lane & 15;
    const int kvs = lane >> 4;  // which 16B k-half

    float SAr[4] = {0.f, 0.f, 0.f, 0.f};
    float Wr[4]  = {0.f, 0.f, 0.f, 0.f};
    float SBr[4] = {0.f, 0.f, 0.f, 0.f};

    for (int jt = 0; jt < JT; ++jt) {
        const int j0 = j0base + jt * BN;

        float acc[2][2][4][4];
#pragma unroll
        for (int m2 = 0; m2 < 2; ++m2)
#pragma unroll
            for (int tm = 0; tm < 2; ++tm)
#pragma unroll
                for (int tn = 0; tn < 4; ++tn)
#pragma unroll
                    for (int c = 0; c < 4; ++c) acc[m2][tm][tn][c] = 0.f;

        // ring-reuse guard across j-tiles (prev tile's last reads must finish)
        __syncthreads();

        // prologue: stages 0..ST-2
#pragma unroll
        for (int p = 0; p < ST - 1; ++p) {
            const int k0 = p * 16;
#pragma unroll
            for (int m = 0; m < 2; ++m)
                cp16(aBase + p * A_STAGE + ((m * 2 + kvb) * BM + r2) * 16,
                     &g_bf[m][(size_t)(i0 + r2) * D + k0 + kvb * 8]);
            cp16(bBase + p * B_STAGE + ((bmat * 2 + bkv) * BN + brow) * 16,
                 &g_bf[bmat][(size_t)(j0 + brow) * D + k0 + bkv * 8]);
            asm volatile("cp.async.commit_group;\n" ::: "memory");
        }

        for (int ks = 0; ks < KS; ++ks) {
            // stage ks complete (<=1 newer group pending), publish to all warps
            asm volatile("cp.async.wait_group 1;\n" ::: "memory");
            __syncthreads();

            // issue stage ks+2 (into buffer (ks+2)%ST, read last iter — safe)
            if (ks + 2 < KS) {
                const int buf = (ks + 2) % ST;
                const int k0 = (ks + 2) * 16;
#pragma unroll
                for (int m = 0; m < 2; ++m)
                    cp16(aBase + buf * A_STAGE + ((m * 2 + kvb) * BM + r2) * 16,
                         &g_bf[m][(size_t)(i0 + r2) * D + k0 + kvb * 8]);
                cp16(bBase + buf * B_STAGE + ((bmat * 2 + bkv) * BN + brow) * 16,
                     &g_bf[bmat][(size_t)(j0 + brow) * D + k0 + bkv * 8]);
            }
            asm volatile("cp.async.commit_group;\n" ::: "memory");

            const int cur = ks % ST;
            uint32_t af[2][2][4];
            uint32_t bfr[2][4][2];
#pragma unroll
            for (int m2 = 0; m2 < 2; ++m2) {
#pragma unroll
                for (int tm = 0; tm < 2; ++tm)
                    ldsm_x4(af[m2][tm],
                            aBase + cur * A_STAGE +
                                ((m2 * 2 + kvs) * BM + wm * 32 + tm * 16 + lrow) * 16);
#pragma unroll
                for (int tp = 0; tp < 2; ++tp) {
                    uint32_t r[4];
                    ldsm_x4(r, bBase + cur * B_STAGE +
                                   ((m2 * 2 + kvs) * BN + wn * 32 + tp * 16 + lrow) * 16);
                    bfr[m2][tp * 2 + 0][0] = r[0];
                    bfr[m2][tp * 2 + 0][1] = r[2];
                    bfr[m2][tp * 2 + 1][0] = r[1];
                    bfr[m2][tp * 2 + 1][1] = r[3];
                }
            }
#pragma unroll
            for (int m2 = 0; m2 < 2; ++m2)
#pragma unroll
                for (int tm = 0; tm < 2; ++tm)
#pragma unroll
                    for (int tn = 0; tn < 4; ++tn)
                        mma_bf16(acc[m2][tm][tn], af[m2][tm],
                                 bfr[m2][tn][0], bfr[m2][tn][1]);
        }

        // fused epilogue: per-row partial sums (registers only)
#pragma unroll
        for (int tm = 0; tm < 2; ++tm)
#pragma unroll
            for (int tn = 0; tn < 4; ++tn)
#pragma unroll
                for (int c = 0; c < 4; ++c) {
                    const int li = tm * 2 + (c >> 1);
                    const float a = -acc[0][tm][tn][c];
                    const float b = -acc[1][tm][tn][c];
                    const float ea = fast_exp(a);
                    const float eb = fast_exp(b);
                    SAr[li] += ea;
                    SBr[li] += eb;
                    Wr[li] = fmaf(ea, a - b, Wr[li]);
                }
    }

    // reduce across the 4 lanes sharing each row
#pragma unroll
    for (int li = 0; li < 4; ++li) {
#pragma unroll
        for (int off = 1; off < 4; off <<= 1) {
            SAr[li] += __shfl_xor_sync(0xffffffffu, SAr[li], off);
            Wr[li]  += __shfl_xor_sync(0xffffffffu, Wr[li], off);
            SBr[li] += __shfl_xor_sync(0xffffffffu, SBr[li], off);
        }
    }
    __syncthreads();
    if (wn == 0 && tg == 0) {
#pragma unroll
        for (int li = 0; li < 4; ++li) {
            const int r = wm * 32 + (li >> 1) * 16 + (li & 1) * 8 + g;
            sred[0][r] = SAr[li];
            sred[1][r] = Wr[li];
            sred[2][r] = SBr[li];
        }
    }
    __syncthreads();
    if (wn == 1 && tg == 0) {
#pragma unroll
        for (int li = 0; li < 4; ++li) {
            const int r = wm * 32 + (li >> 1) * 16 + (li & 1) * 8 + g;
            sred[0][r] += SAr[li];
            sred[1][r] += Wr[li];
            sred[2][r] += SBr[li];
        }
    }
    __syncthreads();
    if (t < BM) {
        g_part[0][js][i0 + t] = sred[0][t];
        g_part[1][js][i0 + t] = sred[1][t];
        g_part[2][js][i0 + t] = sred[2][t];
    }
}

// ---------------------------------------------------------------------------
// Kernel 3: merge j-split partials, per-row KL, deterministic mean
// ---------------------------------------------------------------------------
__global__ void finalize_kernel(float* __restrict__ out) {
    __shared__ float red[256];
    const int t = threadIdx.x;
    float sum = 0.f;
    for (int r = t; r < N; r += 256) {
        float SA = 0.f, W = 0.f, SB = 0.f;
#pragma unroll
        for (int j = 0; j < NJ; ++j) {
            SA += g_part[0][j][r];
            W  += g_part[1][j][r];
            SB += g_part[2][j][r];
        }
        sum += W / SA - logf(SA) + logf(SB);
    }
    red[t] = sum;
    __syncthreads();
    for (int s = 128; s > 0; s >>= 1) {
        if (t < s) red[t] += red[t + s];
        __syncthreads();
    }
    if (t == 0) out[0] = red[0] * (1.0f / (float)N);
}

// ---------------------------------------------------------------------------
extern "C" void kernel_launch(void* const* d_in, const int* in_sizes, int n_in,
                              void* d_out, int out_size) {
    (void)in_sizes; (void)n_in; (void)out_size;
    const float* cd = (const float*)d_in[0];
    const float* ed = (const float*)d_in[1];
    normalize_kernel<<<dim3(N, 2), 128>>>(cd, ed);
    gram_kl_kernel<<<dim3(N / BM, NJ), 256>>>();
    finalize_kernel<<<1, 256>>>((float*)d_out);
}